// round 8
// baseline (speedup 1.0000x reference)
#include <cuda_runtime.h>
#include <math.h>

#define EDIM 512
#define HDIM 64
#define NH   8
#define BATCH 4
#define SEQ  2048
#define MROWS (BATCH*SEQ)   // 8192
#define FFN  2048

// ---------------- scratch (no cudaMalloc allowed) ----------------
__device__ float g_q[MROWS*EDIM];
__device__ float g_k[MROWS*EDIM];
__device__ float g_v[MROWS*EDIM];
__device__ float g_ctx[MROWS*EDIM];
__device__ float g_tmp[MROWS*EDIM];
__device__ float g_ln1[MROWS*EDIM];
__device__ float g_h[MROWS*FFN];

// ---------------- common helpers -------------------------------------------
__device__ __forceinline__ float ex2f(float x) {
    float y;
    asm("ex2.approx.ftz.f32 %0, %1;" : "=f"(y) : "f"(x));
    return y;
}
__device__ __forceinline__ void mma_tf32(float d[4],
                                         const unsigned a[4],
                                         const unsigned b[2]) {
    asm volatile(
        "mma.sync.aligned.m16n8k8.row.col.f32.tf32.tf32.f32 "
        "{%0,%1,%2,%3}, {%4,%5,%6,%7}, {%8,%9}, {%0,%1,%2,%3};\n"
        : "+f"(d[0]), "+f"(d[1]), "+f"(d[2]), "+f"(d[3])
        : "r"(a[0]), "r"(a[1]), "r"(a[2]), "r"(a[3]),
          "r"(b[0]), "r"(b[1]));
}
__device__ __forceinline__ void cp16(void* smem, const void* g) {
    unsigned s = (unsigned)__cvta_generic_to_shared(smem);
    asm volatile("cp.async.ca.shared.global [%0], [%1], 16;\n" :: "r"(s), "l"(g));
}
#define CP_COMMIT asm volatile("cp.async.commit_group;\n")
#define CP_WAIT0  asm volatile("cp.async.wait_group 0;\n")
#define CP_WAIT1  asm volatile("cp.async.wait_group 1;\n")

// =================== TF32 tensor-core GEMM (cp.async 3-stage, BK=32) ========
#define GBM 128
#define GBN 128
#define GBK 32
#define GASTR 36
#define GBSTR 136
#define ABUF (GBM*GASTR)
#define BBUF (GBK*GBSTR)
#define GEMM_SMEM ((3*ABUF + 3*BBUF) * 4)   // 107520 B

template<int DO_GELU>
__global__ void __launch_bounds__(256, 2) gemm_tc(
    const float* __restrict__ A, const float* __restrict__ W,
    const float* __restrict__ bias, float* __restrict__ C,
    int M, int N, int K)
{
    extern __shared__ float sm[];
    float* As = sm;               // [3][ABUF]
    float* Bs = sm + 3*ABUF;      // [3][BBUF]

    const int tid  = threadIdx.x;
    const int wid  = tid >> 5, lane = tid & 31;
    const int g    = lane >> 2, tig = lane & 3;
    const int wm   = wid >> 2,  wn  = wid & 3;
    const int bm0  = blockIdx.y * GBM, bn0 = blockIdx.x * GBN;

    const int ar = tid >> 2,  ac = (tid & 3) * 4;
    const int br = tid >> 4,  bc = (tid & 15) * 4;
    const float* Ag = A + (size_t)(bm0 + ar) * K + ac;
    const float* Wg = W + (size_t)br * N + bn0 + bc;

    float d[4][4][4] = {};
    const int nkt = K / GBK;

    // stage loader
    auto load_stage = [&](int kt, int sbuf) {
        float* Ad = As + sbuf * ABUF;
        float* Bd = Bs + sbuf * BBUF;
        const float* Agn = Ag + (size_t)kt * GBK;
        const float* Wgn = Wg + (size_t)kt * GBK * N;
        cp16(&Ad[ar*GASTR + ac],           Agn);
        cp16(&Ad[ar*GASTR + ac + 16],      Agn + 16);
        cp16(&Ad[(ar+64)*GASTR + ac],      Agn + (size_t)64 * K);
        cp16(&Ad[(ar+64)*GASTR + ac + 16], Agn + (size_t)64 * K + 16);
        cp16(&Bd[br*GBSTR + bc],           Wgn);
        cp16(&Bd[br*GBSTR + bc + 64],      Wgn + 64);
        cp16(&Bd[(br+16)*GBSTR + bc],      Wgn + (size_t)16 * N);
        cp16(&Bd[(br+16)*GBSTR + bc + 64], Wgn + (size_t)16 * N + 64);
        CP_COMMIT;
    };

    // prologue: stages 0, 1
    load_stage(0, 0);
    if (nkt > 1) load_stage(1, 1);

    int cbuf = 0;   // kt % 3
    int lbuf = 2;   // (kt+2) % 3
    for (int kt = 0; kt < nkt; kt++) {
        if (kt + 1 < nkt) { CP_WAIT1; } else { CP_WAIT0; }
        __syncthreads();

        if (kt + 2 < nkt) load_stage(kt + 2, lbuf);

        float* Ab = As + cbuf * ABUF;
        float* Bb = Bs + cbuf * BBUF;
        #pragma unroll
        for (int ks = 0; ks < 4; ks++) {
            unsigned a[4][4];
            #pragma unroll
            for (int mt = 0; mt < 4; mt++) {
                const float* ap = &Ab[(wm*64 + mt*16 + g)*GASTR + ks*8 + tig];
                a[mt][0] = __float_as_uint(ap[0]);
                a[mt][1] = __float_as_uint(ap[8*GASTR]);
                a[mt][2] = __float_as_uint(ap[4]);
                a[mt][3] = __float_as_uint(ap[8*GASTR + 4]);
            }
            unsigned b[4][2];
            #pragma unroll
            for (int nt = 0; nt < 4; nt++) {
                const float* bp = &Bb[(ks*8 + tig)*GBSTR + wn*32 + nt*8 + g];
                b[nt][0] = __float_as_uint(bp[0]);
                b[nt][1] = __float_as_uint(bp[4*GBSTR]);
            }
            #pragma unroll
            for (int mt = 0; mt < 4; mt++)
                #pragma unroll
                for (int nt = 0; nt < 4; nt++)
                    mma_tf32(d[mt][nt], a[mt], b[nt]);
        }
        cbuf = (cbuf == 2) ? 0 : cbuf + 1;
        lbuf = (lbuf == 2) ? 0 : lbuf + 1;
    }

    #pragma unroll
    for (int mt = 0; mt < 4; mt++) {
        #pragma unroll
        for (int nt = 0; nt < 4; nt++) {
            const int col  = bn0 + wn*32 + nt*8 + tig*2;
            const float b0 = bias[col], b1 = bias[col + 1];
            const int row0 = bm0 + wm*64 + mt*16 + g;
            float v0 = d[mt][nt][0] + b0;
            float v1 = d[mt][nt][1] + b1;
            float v2 = d[mt][nt][2] + b0;
            float v3 = d[mt][nt][3] + b1;
            if (DO_GELU) {
                v0 = 0.5f*v0*(1.0f + erff(v0*0.70710678118654752f));
                v1 = 0.5f*v1*(1.0f + erff(v1*0.70710678118654752f));
                v2 = 0.5f*v2*(1.0f + erff(v2*0.70710678118654752f));
                v3 = 0.5f*v3*(1.0f + erff(v3*0.70710678118654752f));
            }
            *(float2*)(C + (size_t)row0 * N + col)       = make_float2(v0, v1);
            *(float2*)(C + (size_t)(row0 + 8) * N + col) = make_float2(v2, v3);
        }
    }
}

// =================== TF32 flash attention (BKV=64, cp.async 2-stage) ========
#define BQ  128
#define BKV 64
#define KSTR 68
#define VSTR 72
#define PSTR 68
#define KBUF (BKV*KSTR)
#define VBUF (BKV*VSTR)
#define ATTN_SMEM ((2*KBUF + 2*VBUF + BQ*PSTR) * 4)

__global__ void __launch_bounds__(256, 2) attn_tc(
    const float* __restrict__ Q, const float* __restrict__ K,
    const float* __restrict__ V, float* __restrict__ O)
{
    extern __shared__ float sm[];
    float* Ks = sm;
    float* Vs = sm + 2*KBUF;
    float* Ps = sm + 2*KBUF + 2*VBUF;

    const int tid  = threadIdx.x;
    const int wid  = tid >> 5, lane = tid & 31;
    const int g    = lane >> 2, tig = lane & 3;
    const int qt = blockIdx.x, h = blockIdx.y, b = blockIdx.z;

    const size_t baseq  = ((size_t)(b*SEQ) + qt*BQ) * EDIM + h*HDIM;
    const size_t basekv = ((size_t)(b*SEQ)) * EDIM + h*HDIM;

    const float qscale = 0.125f * 1.4426950408889634f;
    unsigned qa[8][4];
    {
        const float* qp = Q + baseq + (size_t)(wid*16) * EDIM;
        #pragma unroll
        for (int ks = 0; ks < 8; ks++) {
            const int col = ks*8 + tig;
            qa[ks][0] = __float_as_uint(qp[(size_t)g*EDIM + col] * qscale);
            qa[ks][1] = __float_as_uint(qp[(size_t)(g+8)*EDIM + col] * qscale);
            qa[ks][2] = __float_as_uint(qp[(size_t)g*EDIM + col + 4] * qscale);
            qa[ks][3] = __float_as_uint(qp[(size_t)(g+8)*EDIM + col + 4] * qscale);
        }
    }

    float m0 = -1e30f, m1 = -1e30f, l0 = 0.f, l1 = 0.f;
    float o[8][4];
    #pragma unroll
    for (int nt = 0; nt < 8; nt++)
        #pragma unroll
        for (int j = 0; j < 4; j++) o[nt][j] = 0.f;

    float* Pw = &Ps[(wid*16) * PSTR];

    const int lj = tid >> 2, lc = (tid & 3) * 4;
    const float* Kg0 = K + basekv + (size_t)lj * EDIM + lc;
    const float* Vg0 = V + basekv + (size_t)lj * EDIM + lc;
    const int nTiles = SEQ / BKV;

    #pragma unroll
    for (int i = 0; i < 4; i++) {
        cp16(&Ks[lj*KSTR + lc + i*16], Kg0 + i*16);
        cp16(&Vs[lj*VSTR + lc + i*16], Vg0 + i*16);
    }
    CP_COMMIT;

    for (int t = 0; t < nTiles; t++) {
        const int buf = t & 1;
        const float* Kb = Ks + buf * KBUF;
        const float* Vb = Vs + buf * VBUF;
        CP_WAIT0;
        __syncthreads();

        if (t + 1 < nTiles) {
            float* Kn = Ks + (buf^1) * KBUF;
            float* Vn = Vs + (buf^1) * VBUF;
            const size_t off = (size_t)(t+1) * BKV * EDIM;
            #pragma unroll
            for (int i = 0; i < 4; i++) {
                cp16(&Kn[lj*KSTR + lc + i*16], Kg0 + off + i*16);
                cp16(&Vn[lj*VSTR + lc + i*16], Vg0 + off + i*16);
            }
            CP_COMMIT;
        }

        float s[8][4];
        #pragma unroll
        for (int nt = 0; nt < 8; nt++)
            #pragma unroll
            for (int j = 0; j < 4; j++) s[nt][j] = 0.f;
        #pragma unroll
        for (int ks = 0; ks < 8; ks++) {
            #pragma unroll
            for (int nt = 0; nt < 8; nt++) {
                unsigned bf[2];
                const float* bp = &Kb[(nt*8 + g)*KSTR + ks*8 + tig];
                bf[0] = __float_as_uint(bp[0]);
                bf[1] = __float_as_uint(bp[4]);
                mma_tf32(s[nt], qa[ks], bf);
            }
        }

        float rm0 = -1e30f, rm1 = -1e30f;
        #pragma unroll
        for (int nt = 0; nt < 8; nt++) {
            rm0 = fmaxf(rm0, fmaxf(s[nt][0], s[nt][1]));
            rm1 = fmaxf(rm1, fmaxf(s[nt][2], s[nt][3]));
        }
        #pragma unroll
        for (int off = 1; off < 4; off <<= 1) {
            rm0 = fmaxf(rm0, __shfl_xor_sync(0xffffffffu, rm0, off));
            rm1 = fmaxf(rm1, __shfl_xor_sync(0xffffffffu, rm1, off));
        }
        const float M0 = fmaxf(m0, rm0), M1 = fmaxf(m1, rm1);
        const float a0 = ex2f(m0 - M0), a1 = ex2f(m1 - M1);
        float sum0 = 0.f, sum1 = 0.f;
        #pragma unroll
        for (int nt = 0; nt < 8; nt++) {
            s[nt][0] = ex2f(s[nt][0] - M0);
            s[nt][1] = ex2f(s[nt][1] - M0);
            s[nt][2] = ex2f(s[nt][2] - M1);
            s[nt][3] = ex2f(s[nt][3] - M1);
            sum0 += s[nt][0] + s[nt][1];
            sum1 += s[nt][2] + s[nt][3];
        }
        #pragma unroll
        for (int off = 1; off < 4; off <<= 1) {
            sum0 += __shfl_xor_sync(0xffffffffu, sum0, off);
            sum1 += __shfl_xor_sync(0xffffffffu, sum1, off);
        }
        l0 = l0*a0 + sum0;  l1 = l1*a1 + sum1;
        m0 = M0;            m1 = M1;
        #pragma unroll
        for (int nt = 0; nt < 8; nt++) {
            o[nt][0] *= a0; o[nt][1] *= a0;
            o[nt][2] *= a1; o[nt][3] *= a1;
        }

        #pragma unroll
        for (int nt = 0; nt < 8; nt++) {
            *(float2*)&Pw[g*PSTR + nt*8 + 2*tig]     = make_float2(s[nt][0], s[nt][1]);
            *(float2*)&Pw[(g+8)*PSTR + nt*8 + 2*tig] = make_float2(s[nt][2], s[nt][3]);
        }
        __syncwarp();

        #pragma unroll
        for (int ks = 0; ks < 8; ks++) {
            unsigned pa[4];
            const float* pp = &Pw[g*PSTR + ks*8 + tig];
            pa[0] = __float_as_uint(pp[0]);
            pa[1] = __float_as_uint(pp[8*PSTR]);
            pa[2] = __float_as_uint(pp[4]);
            pa[3] = __float_as_uint(pp[8*PSTR + 4]);
            #pragma unroll
            for (int nt = 0; nt < 8; nt++) {
                unsigned bf[2];
                const float* bp = &Vb[(ks*8 + tig)*VSTR + nt*8 + g];
                bf[0] = __float_as_uint(bp[0]);
                bf[1] = __float_as_uint(bp[4*VSTR]);
                mma_tf32(o[nt], pa, bf);
            }
        }
    }

    const float inv0 = 1.0f / l0, inv1 = 1.0f / l1;
    float* Og = (float*)(O + baseq + (size_t)(wid*16) * EDIM);
    #pragma unroll
    for (int nt = 0; nt < 8; nt++) {
        const int col = nt*8 + 2*tig;
        *(float2*)(Og + (size_t)g*EDIM + col) =
            make_float2(o[nt][0]*inv0, o[nt][1]*inv0);
        *(float2*)(Og + (size_t)(g+8)*EDIM + col) =
            make_float2(o[nt][2]*inv1, o[nt][3]*inv1);
    }
}

// ---------------- fused residual + LayerNorm (warp per row) -----------------
__global__ void __launch_bounds__(256) ln_kernel(
    const float* __restrict__ X, const float* __restrict__ Y,
    const float* __restrict__ gamma, const float* __restrict__ beta,
    float* __restrict__ out)
{
    const int lane = threadIdx.x & 31;
    const int row  = blockIdx.x * 8 + (threadIdx.x >> 5);

    float4 v[4];
    float sum = 0.f, sq = 0.f;
    #pragma unroll
    for (int i = 0; i < 4; i++) {
        const int c = (i*32 + lane) * 4;
        float4 xv = *(const float4*)(X + (size_t)row*EDIM + c);
        float4 yv = *(const float4*)(Y + (size_t)row*EDIM + c);
        v[i].x = xv.x + yv.x; v[i].y = xv.y + yv.y;
        v[i].z = xv.z + yv.z; v[i].w = xv.w + yv.w;
        sum += v[i].x + v[i].y + v[i].z + v[i].w;
        sq  += v[i].x*v[i].x + v[i].y*v[i].y + v[i].z*v[i].z + v[i].w*v[i].w;
    }
    #pragma unroll
    for (int off = 16; off > 0; off >>= 1) {
        sum += __shfl_xor_sync(0xffffffffu, sum, off);
        sq  += __shfl_xor_sync(0xffffffffu, sq, off);
    }
    const float mu   = sum * (1.0f/EDIM);
    const float var  = sq * (1.0f/EDIM) - mu*mu;
    const float rstd = rsqrtf(var + 1e-5f);

    #pragma unroll
    for (int i = 0; i < 4; i++) {
        const int c = (i*32 + lane) * 4;
        float4 gv = *(const float4*)(gamma + c);
        float4 bv = *(const float4*)(beta  + c);
        float4 ov;
        ov.x = (v[i].x - mu)*rstd*gv.x + bv.x;
        ov.y = (v[i].y - mu)*rstd*gv.y + bv.y;
        ov.z = (v[i].z - mu)*rstd*gv.z + bv.z;
        ov.w = (v[i].w - mu)*rstd*gv.w + bv.w;
        *(float4*)(out + (size_t)row*EDIM + c) = ov;
    }
}

// ---------------- launch ----------------------------------------------------
extern "C" void kernel_launch(void* const* d_in, const int* in_sizes, int n_in,
                              void* d_out, int out_size)
{
    const float* query = (const float*)d_in[0];
    const float* key   = (const float*)d_in[1];
    const float* value = (const float*)d_in[2];
    const float* Wq = (const float*)d_in[3];  const float* bq = (const float*)d_in[4];
    const float* Wk = (const float*)d_in[5];  const float* bk = (const float*)d_in[6];
    const float* Wv = (const float*)d_in[7];  const float* bv = (const float*)d_in[8];
    const float* Wo = (const float*)d_in[9];  const float* bo = (const float*)d_in[10];
    const float* g1 = (const float*)d_in[11]; const float* be1 = (const float*)d_in[12];
    const float* g2 = (const float*)d_in[13]; const float* be2 = (const float*)d_in[14];
    const float* W1 = (const float*)d_in[15]; const float* b1 = (const float*)d_in[16];
    const float* W2 = (const float*)d_in[17]; const float* b2 = (const float*)d_in[18];
    float* out = (float*)d_out;

    float *q, *k, *v, *ctx, *tmp, *ln1, *hbuf;
    cudaGetSymbolAddress((void**)&q,    g_q);
    cudaGetSymbolAddress((void**)&k,    g_k);
    cudaGetSymbolAddress((void**)&v,    g_v);
    cudaGetSymbolAddress((void**)&ctx,  g_ctx);
    cudaGetSymbolAddress((void**)&tmp,  g_tmp);
    cudaGetSymbolAddress((void**)&ln1,  g_ln1);
    cudaGetSymbolAddress((void**)&hbuf, g_h);

    cudaFuncSetAttribute(gemm_tc<0>, cudaFuncAttributeMaxDynamicSharedMemorySize, GEMM_SMEM);
    cudaFuncSetAttribute(gemm_tc<1>, cudaFuncAttributeMaxDynamicSharedMemorySize, GEMM_SMEM);
    cudaFuncSetAttribute(attn_tc,    cudaFuncAttributeMaxDynamicSharedMemorySize, ATTN_SMEM);

    dim3 gProj(EDIM/GBN, MROWS/GBM);   // 4 x 64
    dim3 gF1(FFN/GBN,  MROWS/GBM);     // 16 x 64

    gemm_tc<0><<<gProj, 256, GEMM_SMEM>>>(query, Wq, bq, q, MROWS, EDIM, EDIM);
    gemm_tc<0><<<gProj, 256, GEMM_SMEM>>>(key,   Wk, bk, k, MROWS, EDIM, EDIM);
    gemm_tc<0><<<gProj, 256, GEMM_SMEM>>>(value, Wv, bv, v, MROWS, EDIM, EDIM);

    attn_tc<<<dim3(SEQ/BQ, NH, BATCH), 256, ATTN_SMEM>>>(q, k, v, ctx);

    gemm_tc<0><<<gProj, 256, GEMM_SMEM>>>(ctx, Wo, bo, tmp, MROWS, EDIM, EDIM);
    ln_kernel<<<MROWS/8, 256>>>(query, tmp, g1, be1, ln1);

    gemm_tc<1><<<gF1, 256, GEMM_SMEM>>>(ln1, W1, b1, hbuf, MROWS, FFN, EDIM);
    gemm_tc<0><<<gProj, 256, GEMM_SMEM>>>(hbuf, W2, b2, tmp, MROWS, EDIM, FFN);
    ln_kernel<<<MROWS/8, 256>>>(ln1, tmp, g2, be2, out);
}

// round 9
// speedup vs baseline: 1.7379x; 1.7379x over previous
#include <cuda_runtime.h>
#include <cuda_fp16.h>
#include <math.h>
#include <stdint.h>

#define EDIM 512
#define HDIM 64
#define NH   8
#define BATCH 4
#define SEQ  2048
#define MROWS (BATCH*SEQ)   // 8192
#define FFN  2048
#define QSCALE 0.18033688011112042f   // 0.125 * log2(e)

// ---------------- scratch (no cudaMalloc allowed) ----------------
__device__ __half g_qin_h[MROWS*EDIM];
__device__ __half g_kin_h[MROWS*EDIM];
__device__ __half g_vin_h[MROWS*EDIM];
__device__ __half g_qh[MROWS*EDIM];      // scaled Q (proj out)
__device__ __half g_kh[MROWS*EDIM];
__device__ __half g_vt[MROWS*EDIM];      // V^T [b][h][d][s]
__device__ __half g_ctxh[MROWS*EDIM];
__device__ float  g_tmp[MROWS*EDIM];
__device__ float  g_ln1[MROWS*EDIM];
__device__ __half g_ln1h[MROWS*EDIM];
__device__ __half g_hh[MROWS*FFN];
__device__ __half g_wt[4*EDIM*EDIM + 2*EDIM*FFN];   // transposed half weights

// ---------------- helpers ---------------------------------------------------
__device__ __forceinline__ float ex2f(float x) {
    float y; asm("ex2.approx.ftz.f32 %0, %1;" : "=f"(y) : "f"(x)); return y;
}
__device__ __forceinline__ void mma_f16(float d[4],
                                        const unsigned a[4],
                                        const unsigned b[2]) {
    asm volatile(
        "mma.sync.aligned.m16n8k16.row.col.f32.f16.f16.f32 "
        "{%0,%1,%2,%3}, {%4,%5,%6,%7}, {%8,%9}, {%0,%1,%2,%3};\n"
        : "+f"(d[0]), "+f"(d[1]), "+f"(d[2]), "+f"(d[3])
        : "r"(a[0]), "r"(a[1]), "r"(a[2]), "r"(a[3]),
          "r"(b[0]), "r"(b[1]));
}
__device__ __forceinline__ void cp16(void* smem, const void* g) {
    unsigned s = (unsigned)__cvta_generic_to_shared(smem);
    asm volatile("cp.async.ca.shared.global [%0], [%1], 16;\n" :: "r"(s), "l"(g));
}
#define CP_COMMIT asm volatile("cp.async.commit_group;\n")
#define CP_WAIT0  asm volatile("cp.async.wait_group 0;\n")
__device__ __forceinline__ unsigned h2u(float a, float b) {
    __half2 h = __floats2half2_rn(a, b);
    return *(unsigned*)&h;
}

// ============== FP16 tensor-core GEMM: C = A[M,K] @ Wt[N,K]^T + bias ========
// 128x128x32 tiles, 256 thr = 8 warps (2m x 4n), warp 64x32, 2-stage cp.async.
// MODE: 0=float out, 1=half out, 2=half*QSCALE, 3=half V^T out, 4=half+GELU
#define AST 40                 // halves/row: word perm (20g+tig) conflict-free
#define TBUF (128*AST)         // 5120 halves per operand per stage
#define GEMM_SMEM (4*TBUF*2)   // 40960 B

template<int MODE>
__global__ void __launch_bounds__(256, 2) gemm_h(
    const __half* __restrict__ A, const __half* __restrict__ Wt,
    const float* __restrict__ bias, void* __restrict__ Cout,
    int M, int N, int K)
{
    extern __shared__ __half hsm[];
    __half* As = hsm;            // [2][TBUF]
    __half* Bs = hsm + 2*TBUF;   // [2][TBUF]

    const int tid  = threadIdx.x;
    const int wid  = tid >> 5, lane = tid & 31;
    const int g    = lane >> 2, tig = lane & 3;
    const int wm   = wid >> 2,  wn  = wid & 3;
    const int bm0  = blockIdx.y * 128, bn0 = blockIdx.x * 128;

    const int lr = tid >> 2, lch = tid & 3;     // rows lr, lr+64; 16B chunks
    const __half* Ag = A  + (size_t)(bm0 + lr) * K + lch*8;
    const __half* Wg = Wt + (size_t)(bn0 + lr) * K + lch*8;

    float d[4][4][4] = {};
    const int nkt = K / 32;

    auto load_stage = [&](int kt, int sbuf) {
        __half* Ad = As + sbuf * TBUF;
        __half* Bd = Bs + sbuf * TBUF;
        const __half* Agn = Ag + (size_t)kt * 32;
        const __half* Wgn = Wg + (size_t)kt * 32;
        cp16(&Ad[lr*AST + lch*8],      Agn);
        cp16(&Ad[(lr+64)*AST + lch*8], Agn + (size_t)64 * K);
        cp16(&Bd[lr*AST + lch*8],      Wgn);
        cp16(&Bd[(lr+64)*AST + lch*8], Wgn + (size_t)64 * K);
        CP_COMMIT;
    };

    load_stage(0, 0);

    for (int kt = 0; kt < nkt; kt++) {
        const int buf = kt & 1;
        CP_WAIT0;
        __syncthreads();
        if (kt + 1 < nkt) load_stage(kt + 1, buf ^ 1);

        const __half* Ab = As + buf * TBUF;
        const __half* Bb = Bs + buf * TBUF;
        #pragma unroll
        for (int ks = 0; ks < 2; ks++) {
            const int k0 = ks*16 + 2*tig;
            unsigned a[4][4];
            #pragma unroll
            for (int mt = 0; mt < 4; mt++) {
                const __half* ap = &Ab[(wm*64 + mt*16 + g)*AST + k0];
                a[mt][0] = *(const unsigned*)(ap);
                a[mt][1] = *(const unsigned*)(ap + 8*AST);
                a[mt][2] = *(const unsigned*)(ap + 8);
                a[mt][3] = *(const unsigned*)(ap + 8*AST + 8);
            }
            unsigned b[4][2];
            #pragma unroll
            for (int nt = 0; nt < 4; nt++) {
                const __half* bp = &Bb[(wn*32 + nt*8 + g)*AST + k0];
                b[nt][0] = *(const unsigned*)(bp);
                b[nt][1] = *(const unsigned*)(bp + 8);
            }
            #pragma unroll
            for (int mt = 0; mt < 4; mt++)
                #pragma unroll
                for (int nt = 0; nt < 4; nt++)
                    mma_f16(d[mt][nt], a[mt], b[nt]);
        }
    }

    if (MODE == 3) __syncthreads();   // about to reuse smem for staging

    #pragma unroll
    for (int mt = 0; mt < 4; mt++) {
        #pragma unroll
        for (int nt = 0; nt < 4; nt++) {
            const int lc   = wn*32 + nt*8 + 2*tig;
            const int col  = bn0 + lc;
            const float b0 = bias[col], b1 = bias[col + 1];
            const int r0l  = wm*64 + mt*16 + g;
            const int row0 = bm0 + r0l;
            float v0 = d[mt][nt][0] + b0;
            float v1 = d[mt][nt][1] + b1;
            float v2 = d[mt][nt][2] + b0;
            float v3 = d[mt][nt][3] + b1;
            if (MODE == 4) {
                v0 = 0.5f*v0*(1.0f + erff(v0*0.70710678118654752f));
                v1 = 0.5f*v1*(1.0f + erff(v1*0.70710678118654752f));
                v2 = 0.5f*v2*(1.0f + erff(v2*0.70710678118654752f));
                v3 = 0.5f*v3*(1.0f + erff(v3*0.70710678118654752f));
            }
            if (MODE == 2) { v0 *= QSCALE; v1 *= QSCALE; v2 *= QSCALE; v3 *= QSCALE; }
            if (MODE == 0) {
                float* C = (float*)Cout;
                *(float2*)(C + (size_t)row0 * N + col)       = make_float2(v0, v1);
                *(float2*)(C + (size_t)(row0 + 8) * N + col) = make_float2(v2, v3);
            } else if (MODE == 3) {
                __half* st = hsm;   // [128 cols][136]
                st[lc*136 + r0l]         = __float2half(v0);
                st[(lc+1)*136 + r0l]     = __float2half(v1);
                st[lc*136 + r0l + 8]     = __float2half(v2);
                st[(lc+1)*136 + r0l + 8] = __float2half(v3);
            } else {
                __half* C = (__half*)Cout;
                *(unsigned*)(C + (size_t)row0 * N + col)       = h2u(v0, v1);
                *(unsigned*)(C + (size_t)(row0 + 8) * N + col) = h2u(v2, v3);
            }
        }
    }

    if (MODE == 3) {   // staged transposed store -> vt[b][h][d][s]
        __syncthreads();
        __half* st = hsm;
        __half* vt = (__half*)Cout;
        const int bb = bm0 >> 11;       // / SEQ
        const int s0 = bm0 & (SEQ - 1);
        #pragma unroll
        for (int i = 0; i < 8; i++) {
            const int j  = tid + i*256;        // 0..2047
            const int c  = j >> 4, ch = j & 15;
            const int cg = bn0 + c;
            const int hh = cg >> 6, dd = cg & 63;
            const size_t dst = (((size_t)bb*NH + hh)*HDIM + dd)*SEQ + s0 + ch*8;
            *(uint4*)(vt + dst) = *(const uint4*)&st[c*136 + ch*8];
        }
    }
}

// ============== FP16 flash attention (BQ=128, BKV=64, 2-stage) ==============
// K in [key][d] halves (stride 72), V^T in [d][key] (stride 72), P half (72).
#define BQ  128
#define BKV 64
#define AKST 72
#define KBUFH (BKV*AKST)            // 4608 halves
#define ATTN_SMEM ((4*KBUFH + BQ*AKST) * 2)   // 55296 B

__global__ void __launch_bounds__(256, 2) attn_h(
    const __half* __restrict__ Q, const __half* __restrict__ K,
    const __half* __restrict__ VT, __half* __restrict__ O)
{
    extern __shared__ __half hsm[];
    __half* Ks = hsm;                 // [2][KBUFH]
    __half* Vs = hsm + 2*KBUFH;       // [2][KBUFH]
    __half* Ps = hsm + 4*KBUFH;       // [BQ][AKST]

    const int tid  = threadIdx.x;
    const int wid  = tid >> 5, lane = tid & 31;
    const int g    = lane >> 2, tig = lane & 3;
    const int qt = blockIdx.x, h = blockIdx.y, b = blockIdx.z;

    const size_t baseq  = ((size_t)(b*SEQ) + qt*BQ) * EDIM + h*HDIM;
    const size_t vtbase = ((size_t)(b*NH + h)) * HDIM * SEQ;

    // Q fragments (Q already scaled by QSCALE at projection epilogue)
    unsigned qa[4][4];
    {
        const __half* qp = Q + baseq + (size_t)(wid*16) * EDIM;
        #pragma unroll
        for (int ks = 0; ks < 4; ks++) {
            const int k0 = ks*16 + 2*tig;
            qa[ks][0] = *(const unsigned*)(qp + (size_t)g*EDIM + k0);
            qa[ks][1] = *(const unsigned*)(qp + (size_t)(g+8)*EDIM + k0);
            qa[ks][2] = *(const unsigned*)(qp + (size_t)g*EDIM + k0 + 8);
            qa[ks][3] = *(const unsigned*)(qp + (size_t)(g+8)*EDIM + k0 + 8);
        }
    }

    float m0 = -1e30f, m1 = -1e30f, l0 = 0.f, l1 = 0.f;
    float o[8][4];
    #pragma unroll
    for (int nt = 0; nt < 8; nt++)
        #pragma unroll
        for (int j = 0; j < 4; j++) o[nt][j] = 0.f;

    __half* Pw = &Ps[(wid*16) * AKST];

    // loaders: 64 rows x 64 halves (8 chunks of 16B); rows lj, lj+32
    const int lj = tid >> 3, lch = tid & 7;
    const __half* Kg0 = K  + ((size_t)(b*SEQ)) * EDIM + h*HDIM + (size_t)lj * EDIM + lch*8;
    const __half* Vg0 = VT + vtbase + (size_t)lj * SEQ + lch*8;
    const int nTiles = SEQ / BKV;

    #pragma unroll
    for (int i = 0; i < 2; i++) {
        cp16(&Ks[(lj + i*32)*AKST + lch*8], Kg0 + (size_t)(i*32) * EDIM);
        cp16(&Vs[(lj + i*32)*AKST + lch*8], Vg0 + (size_t)(i*32) * SEQ);
    }
    CP_COMMIT;

    for (int t = 0; t < nTiles; t++) {
        const int buf = t & 1;
        const __half* Kb = Ks + buf * KBUFH;
        const __half* Vb = Vs + buf * KBUFH;
        CP_WAIT0;
        __syncthreads();

        if (t + 1 < nTiles) {
            __half* Kn = Ks + (buf^1) * KBUFH;
            __half* Vn = Vs + (buf^1) * KBUFH;
            const size_t koff = (size_t)(t+1) * BKV * EDIM;
            const size_t voff = (size_t)(t+1) * BKV;   // keys along s
            #pragma unroll
            for (int i = 0; i < 2; i++) {
                cp16(&Kn[(lj + i*32)*AKST + lch*8], Kg0 + koff + (size_t)(i*32) * EDIM);
                cp16(&Vn[(lj + i*32)*AKST + lch*8], Vg0 + voff + (size_t)(i*32) * SEQ);
            }
            CP_COMMIT;
        }

        // S = Q @ K^T  (m16 x n64, k=64 via 4 k16 steps)
        float s[8][4];
        #pragma unroll
        for (int nt = 0; nt < 8; nt++)
            #pragma unroll
            for (int j = 0; j < 4; j++) s[nt][j] = 0.f;
        #pragma unroll
        for (int ks = 0; ks < 4; ks++) {
            const int k0 = ks*16 + 2*tig;
            #pragma unroll
            for (int nt = 0; nt < 8; nt++) {
                unsigned bf[2];
                const __half* bp = &Kb[(nt*8 + g)*AKST + k0];
                bf[0] = *(const unsigned*)(bp);
                bf[1] = *(const unsigned*)(bp + 8);
                mma_f16(s[nt], qa[ks], bf);
            }
        }

        // online softmax (log2 domain), rows g / g+8
        float rm0 = -1e30f, rm1 = -1e30f;
        #pragma unroll
        for (int nt = 0; nt < 8; nt++) {
            rm0 = fmaxf(rm0, fmaxf(s[nt][0], s[nt][1]));
            rm1 = fmaxf(rm1, fmaxf(s[nt][2], s[nt][3]));
        }
        #pragma unroll
        for (int off = 1; off < 4; off <<= 1) {
            rm0 = fmaxf(rm0, __shfl_xor_sync(0xffffffffu, rm0, off));
            rm1 = fmaxf(rm1, __shfl_xor_sync(0xffffffffu, rm1, off));
        }
        const float M0 = fmaxf(m0, rm0), M1 = fmaxf(m1, rm1);
        const float a0 = ex2f(m0 - M0), a1 = ex2f(m1 - M1);
        float sum0 = 0.f, sum1 = 0.f;
        #pragma unroll
        for (int nt = 0; nt < 8; nt++) {
            s[nt][0] = ex2f(s[nt][0] - M0);
            s[nt][1] = ex2f(s[nt][1] - M0);
            s[nt][2] = ex2f(s[nt][2] - M1);
            s[nt][3] = ex2f(s[nt][3] - M1);
            sum0 += s[nt][0] + s[nt][1];
            sum1 += s[nt][2] + s[nt][3];
        }
        #pragma unroll
        for (int off = 1; off < 4; off <<= 1) {
            sum0 += __shfl_xor_sync(0xffffffffu, sum0, off);
            sum1 += __shfl_xor_sync(0xffffffffu, sum1, off);
        }
        l0 = l0*a0 + sum0;  l1 = l1*a1 + sum1;
        m0 = M0;            m1 = M1;
        #pragma unroll
        for (int nt = 0; nt < 8; nt++) {
            o[nt][0] *= a0; o[nt][1] *= a0;
            o[nt][2] *= a1; o[nt][3] *= a1;
        }

        // store P as packed half pairs (warp-private rows)
        #pragma unroll
        for (int nt = 0; nt < 8; nt++) {
            *(unsigned*)&Pw[g*AKST + nt*8 + 2*tig]     = h2u(s[nt][0], s[nt][1]);
            *(unsigned*)&Pw[(g+8)*AKST + nt*8 + 2*tig] = h2u(s[nt][2], s[nt][3]);
        }
        __syncwarp();

        // O += P @ V  (V^T rows = d; m16 x n64, k=64 keys via 4 k16 steps)
        #pragma unroll
        for (int ks = 0; ks < 4; ks++) {
            const int k0 = ks*16 + 2*tig;
            unsigned pa[4];
            const __half* pp = &Pw[g*AKST + k0];
            pa[0] = *(const unsigned*)(pp);
            pa[1] = *(const unsigned*)(pp + 8*AKST);
            pa[2] = *(const unsigned*)(pp + 8);
            pa[3] = *(const unsigned*)(pp + 8*AKST + 8);
            #pragma unroll
            for (int nt = 0; nt < 8; nt++) {
                unsigned bf[2];
                const __half* bp = &Vb[(nt*8 + g)*AKST + k0];
                bf[0] = *(const unsigned*)(bp);
                bf[1] = *(const unsigned*)(bp + 8);
                mma_f16(o[nt], pa, bf);
            }
        }
    }

    const float inv0 = 1.0f / l0, inv1 = 1.0f / l1;
    __half* Og = O + baseq + (size_t)(wid*16) * EDIM;
    #pragma unroll
    for (int nt = 0; nt < 8; nt++) {
        const int col = nt*8 + 2*tig;
        *(unsigned*)(Og + (size_t)g*EDIM + col)     = h2u(o[nt][0]*inv0, o[nt][1]*inv0);
        *(unsigned*)(Og + (size_t)(g+8)*EDIM + col) = h2u(o[nt][2]*inv1, o[nt][3]*inv1);
    }
}

// ---------------- fused residual + LayerNorm (warp per row) -----------------
template<int WRITE_HALF>
__global__ void __launch_bounds__(256) ln_kernel(
    const float* __restrict__ X, const float* __restrict__ Y,
    const float* __restrict__ gamma, const float* __restrict__ beta,
    float* __restrict__ outF, __half* __restrict__ outH)
{
    const int lane = threadIdx.x & 31;
    const int row  = blockIdx.x * 8 + (threadIdx.x >> 5);

    float4 v[4];
    float sum = 0.f, sq = 0.f;
    #pragma unroll
    for (int i = 0; i < 4; i++) {
        const int c = (i*32 + lane) * 4;
        float4 xv = *(const float4*)(X + (size_t)row*EDIM + c);
        float4 yv = *(const float4*)(Y + (size_t)row*EDIM + c);
        v[i].x = xv.x + yv.x; v[i].y = xv.y + yv.y;
        v[i].z = xv.z + yv.z; v[i].w = xv.w + yv.w;
        sum += v[i].x + v[i].y + v[i].z + v[i].w;
        sq  += v[i].x*v[i].x + v[i].y*v[i].y + v[i].z*v[i].z + v[i].w*v[i].w;
    }
    #pragma unroll
    for (int off = 16; off > 0; off >>= 1) {
        sum += __shfl_xor_sync(0xffffffffu, sum, off);
        sq  += __shfl_xor_sync(0xffffffffu, sq, off);
    }
    const float mu   = sum * (1.0f/EDIM);
    const float var  = sq * (1.0f/EDIM) - mu*mu;
    const float rstd = rsqrtf(var + 1e-5f);

    #pragma unroll
    for (int i = 0; i < 4; i++) {
        const int c = (i*32 + lane) * 4;
        float4 gv = *(const float4*)(gamma + c);
        float4 bv = *(const float4*)(beta  + c);
        float4 ov;
        ov.x = (v[i].x - mu)*rstd*gv.x + bv.x;
        ov.y = (v[i].y - mu)*rstd*gv.y + bv.y;
        ov.z = (v[i].z - mu)*rstd*gv.z + bv.z;
        ov.w = (v[i].w - mu)*rstd*gv.w + bv.w;
        *(float4*)(outF + (size_t)row*EDIM + c) = ov;
        if (WRITE_HALF) {
            *(unsigned*)(outH + (size_t)row*EDIM + c)     = h2u(ov.x, ov.y);
            *(unsigned*)(outH + (size_t)row*EDIM + c + 2) = h2u(ov.z, ov.w);
        }
    }
}

// ---------------- converts --------------------------------------------------
__global__ void __launch_bounds__(256) f2h(const float* __restrict__ in,
                                           __half* __restrict__ out, int n)
{
    const int i = (blockIdx.x * 256 + threadIdx.x) * 4;
    if (i >= n) return;
    float4 v = *(const float4*)(in + i);
    *(unsigned*)(out + i)     = h2u(v.x, v.y);
    *(unsigned*)(out + i + 2) = h2u(v.z, v.w);
}

// W fp32 [K,N] -> half [N,K]
__global__ void __launch_bounds__(256) tconv(const float* __restrict__ in,
                                             __half* __restrict__ out, int K, int N)
{
    __shared__ float t[32][33];
    const int bx = blockIdx.x * 32;   // N
    const int by = blockIdx.y * 32;   // K
    const int x = threadIdx.x & 31, y = threadIdx.x >> 5;
    #pragma unroll
    for (int i = 0; i < 32; i += 8)
        t[y + i][x] = in[(size_t)(by + y + i)*N + bx + x];
    __syncthreads();
    #pragma unroll
    for (int i = 0; i < 32; i += 8)
        out[(size_t)(bx + y + i)*K + by + x] = __float2half(t[x][y + i]);
}

// ---------------- launch ----------------------------------------------------
extern "C" void kernel_launch(void* const* d_in, const int* in_sizes, int n_in,
                              void* d_out, int out_size)
{
    const float* query = (const float*)d_in[0];
    const float* key   = (const float*)d_in[1];
    const float* value = (const float*)d_in[2];
    const float* Wq = (const float*)d_in[3];  const float* bq = (const float*)d_in[4];
    const float* Wk = (const float*)d_in[5];  const float* bk = (const float*)d_in[6];
    const float* Wv = (const float*)d_in[7];  const float* bv = (const float*)d_in[8];
    const float* Wo = (const float*)d_in[9];  const float* bo = (const float*)d_in[10];
    const float* g1 = (const float*)d_in[11]; const float* be1 = (const float*)d_in[12];
    const float* g2 = (const float*)d_in[13]; const float* be2 = (const float*)d_in[14];
    const float* W1 = (const float*)d_in[15]; const float* b1 = (const float*)d_in[16];
    const float* W2 = (const float*)d_in[17]; const float* b2 = (const float*)d_in[18];
    float* out = (float*)d_out;

    __half *qin, *kin, *vin, *qh, *kh, *vt, *ctxh, *ln1h, *hh, *wt;
    float  *tmp, *ln1;
    cudaGetSymbolAddress((void**)&qin,  g_qin_h);
    cudaGetSymbolAddress((void**)&kin,  g_kin_h);
    cudaGetSymbolAddress((void**)&vin,  g_vin_h);
    cudaGetSymbolAddress((void**)&qh,   g_qh);
    cudaGetSymbolAddress((void**)&kh,   g_kh);
    cudaGetSymbolAddress((void**)&vt,   g_vt);
    cudaGetSymbolAddress((void**)&ctxh, g_ctxh);
    cudaGetSymbolAddress((void**)&tmp,  g_tmp);
    cudaGetSymbolAddress((void**)&ln1,  g_ln1);
    cudaGetSymbolAddress((void**)&ln1h, g_ln1h);
    cudaGetSymbolAddress((void**)&hh,   g_hh);
    cudaGetSymbolAddress((void**)&wt,   g_wt);

    __half* WqT = wt;
    __half* WkT = wt + 1*EDIM*EDIM;
    __half* WvT = wt + 2*EDIM*EDIM;
    __half* WoT = wt + 3*EDIM*EDIM;
    __half* W1T = wt + 4*EDIM*EDIM;               // [FFN, EDIM]
    __half* W2T = wt + 4*EDIM*EDIM + EDIM*FFN;    // [EDIM, FFN]

    cudaFuncSetAttribute(gemm_h<0>, cudaFuncAttributeMaxDynamicSharedMemorySize, GEMM_SMEM);
    cudaFuncSetAttribute(gemm_h<1>, cudaFuncAttributeMaxDynamicSharedMemorySize, GEMM_SMEM);
    cudaFuncSetAttribute(gemm_h<2>, cudaFuncAttributeMaxDynamicSharedMemorySize, GEMM_SMEM);
    cudaFuncSetAttribute(gemm_h<3>, cudaFuncAttributeMaxDynamicSharedMemorySize, GEMM_SMEM);
    cudaFuncSetAttribute(gemm_h<4>, cudaFuncAttributeMaxDynamicSharedMemorySize, GEMM_SMEM);
    cudaFuncSetAttribute(attn_h,    cudaFuncAttributeMaxDynamicSharedMemorySize, ATTN_SMEM);

    const int NE = MROWS*EDIM;
    f2h<<<NE/1024, 256>>>(query, qin, NE);
    f2h<<<NE/1024, 256>>>(key,   kin, NE);
    f2h<<<NE/1024, 256>>>(value, vin, NE);
    tconv<<<dim3(EDIM/32, EDIM/32), 256>>>(Wq, WqT, EDIM, EDIM);
    tconv<<<dim3(EDIM/32, EDIM/32), 256>>>(Wk, WkT, EDIM, EDIM);
    tconv<<<dim3(EDIM/32, EDIM/32), 256>>>(Wv, WvT, EDIM, EDIM);
    tconv<<<dim3(EDIM/32, EDIM/32), 256>>>(Wo, WoT, EDIM, EDIM);
    tconv<<<dim3(FFN/32,  EDIM/32), 256>>>(W1, W1T, EDIM, FFN);
    tconv<<<dim3(EDIM/32, FFN/32),  256>>>(W2, W2T, FFN, EDIM);

    dim3 gProj(EDIM/128, MROWS/128);   // 4 x 64
    dim3 gF1(FFN/128,  MROWS/128);     // 16 x 64

    gemm_h<2><<<gProj, 256, GEMM_SMEM>>>(qin, WqT, bq, qh, MROWS, EDIM, EDIM);
    gemm_h<1><<<gProj, 256, GEMM_SMEM>>>(kin, WkT, bk, kh, MROWS, EDIM, EDIM);
    gemm_h<3><<<gProj, 256, GEMM_SMEM>>>(vin, WvT, bv, vt, MROWS, EDIM, EDIM);

    attn_h<<<dim3(SEQ/BQ, NH, BATCH), 256, ATTN_SMEM>>>(qh, kh, vt, ctxh);

    gemm_h<0><<<gProj, 256, GEMM_SMEM>>>(ctxh, WoT, bo, tmp, MROWS, EDIM, EDIM);
    ln_kernel<1><<<MROWS/8, 256>>>(query, tmp, g1, be1, ln1, ln1h);

    gemm_h<4><<<gF1, 256, GEMM_SMEM>>>(ln1h, W1T, b1, hh, MROWS, FFN, EDIM);
    gemm_h<0><<<gProj, 256, GEMM_SMEM>>>(hh, W2T, b2, tmp, MROWS, EDIM, FFN);
    ln_kernel<0><<<MROWS/8, 256>>>(ln1, tmp, g2, be2, out, nullptr);
}

// round 11
// speedup vs baseline: 1.9024x; 1.0947x over previous
#include <cuda_runtime.h>
#include <cuda_fp16.h>
#include <math.h>
#include <stdint.h>

#define EDIM 512
#define HDIM 64
#define NH   8
#define BATCH 4
#define SEQ  2048
#define MROWS (BATCH*SEQ)   // 8192
#define FFN  2048
#define QSCALE 0.18033688011112042f   // 0.125 * log2(e)

// ---------------- scratch (no cudaMalloc allowed) ----------------
__device__ __half g_qin_h[MROWS*EDIM];
__device__ __half g_kin_h[MROWS*EDIM];
__device__ __half g_vin_h[MROWS*EDIM];
__device__ __half g_qh[MROWS*EDIM];
__device__ __half g_kh[MROWS*EDIM];
__device__ __half g_vt[MROWS*EDIM];      // V^T [b][h][d][s]
__device__ __half g_ctxh[MROWS*EDIM];
__device__ float  g_tmp[MROWS*EDIM];
__device__ float  g_ln1[MROWS*EDIM];
__device__ __half g_ln1h[MROWS*EDIM];
__device__ __half g_hh[MROWS*FFN];
__device__ __half g_wt[4*EDIM*EDIM + 2*EDIM*FFN];

// ---------------- helpers ---------------------------------------------------
__device__ __forceinline__ float ex2f(float x) {
    float y; asm("ex2.approx.ftz.f32 %0, %1;" : "=f"(y) : "f"(x)); return y;
}
__device__ __forceinline__ void mma_f16(float d[4],
                                        const unsigned a[4],
                                        const unsigned b[2]) {
    asm volatile(
        "mma.sync.aligned.m16n8k16.row.col.f32.f16.f16.f32 "
        "{%0,%1,%2,%3}, {%4,%5,%6,%7}, {%8,%9}, {%0,%1,%2,%3};\n"
        : "+f"(d[0]), "+f"(d[1]), "+f"(d[2]), "+f"(d[3])
        : "r"(a[0]), "r"(a[1]), "r"(a[2]), "r"(a[3]),
          "r"(b[0]), "r"(b[1]));
}
__device__ __forceinline__ void ldsm4(unsigned r[4], uint32_t a) {
    asm volatile("ldmatrix.sync.aligned.m8n8.x4.shared.b16 {%0,%1,%2,%3}, [%4];"
        : "=r"(r[0]), "=r"(r[1]), "=r"(r[2]), "=r"(r[3]) : "r"(a));
}
__device__ __forceinline__ void stsm4(uint32_t a, unsigned r0, unsigned r1,
                                      unsigned r2, unsigned r3) {
    asm volatile("stmatrix.sync.aligned.m8n8.x4.shared.b16 [%0], {%1,%2,%3,%4};"
        :: "r"(a), "r"(r0), "r"(r1), "r"(r2), "r"(r3) : "memory");
}
__device__ __forceinline__ void cp16(void* smem, const void* g) {
    unsigned s = (unsigned)__cvta_generic_to_shared(smem);
    asm volatile("cp.async.ca.shared.global [%0], [%1], 16;\n" :: "r"(s), "l"(g));
}
#define CP_COMMIT asm volatile("cp.async.commit_group;\n")
#define CP_WAIT0  asm volatile("cp.async.wait_group 0;\n")
__device__ __forceinline__ unsigned h2u(float a, float b) {
    __half2 h = __floats2half2_rn(a, b);
    return *(unsigned*)&h;
}

// ============== FP16 tensor-core GEMM: C = A[M,K] @ Wt[N,K]^T + bias ========
// MODE: 0=float out, 1=half out, 2=half*QSCALE, 3=half V^T out, 4=half+GELU
#define AST 40
#define TBUF (128*AST)
#define GEMM_SMEM (4*TBUF*2)   // 40960 B

template<int MODE>
__global__ void __launch_bounds__(256, 2) gemm_h(
    const __half* __restrict__ A, const __half* __restrict__ Wt,
    const float* __restrict__ bias, void* __restrict__ Cout,
    int M, int N, int K)
{
    extern __shared__ __half hsm[];
    __half* As = hsm;
    __half* Bs = hsm + 2*TBUF;

    const int tid  = threadIdx.x;
    const int wid  = tid >> 5, lane = tid & 31;
    const int g    = lane >> 2, tig = lane & 3;
    const int wm   = wid >> 2,  wn  = wid & 3;
    const int bm0  = blockIdx.y * 128, bn0 = blockIdx.x * 128;

    const uint32_t smemU = (uint32_t)__cvta_generic_to_shared(hsm);
    const uint32_t AsU = smemU;
    const uint32_t BsU = smemU + 2*TBUF*2;
    // ldmatrix lane offsets: A-pattern (row+8 on lane&8, col+8 on (lane>>1)&8),
    //                        B-pattern (row+8 on (lane>>1)&8, col+8 on lane&8)
    const uint32_t aOff = (((lane&7) + (lane&8))*AST + ((lane>>1)&8))*2;
    const uint32_t bOff = (((lane&7) + ((lane>>1)&8))*AST + (lane&8))*2;

    const int lr = tid >> 2, lch = tid & 3;
    const __half* Ag = A  + (size_t)(bm0 + lr) * K + lch*8;
    const __half* Wg = Wt + (size_t)(bn0 + lr) * K + lch*8;

    float d[4][4][4] = {};
    const int nkt = K / 32;

    auto load_stage = [&](int kt, int sbuf) {
        __half* Ad = As + sbuf * TBUF;
        __half* Bd = Bs + sbuf * TBUF;
        const __half* Agn = Ag + (size_t)kt * 32;
        const __half* Wgn = Wg + (size_t)kt * 32;
        cp16(&Ad[lr*AST + lch*8],      Agn);
        cp16(&Ad[(lr+64)*AST + lch*8], Agn + (size_t)64 * K);
        cp16(&Bd[lr*AST + lch*8],      Wgn);
        cp16(&Bd[(lr+64)*AST + lch*8], Wgn + (size_t)64 * K);
        CP_COMMIT;
    };

    load_stage(0, 0);

    for (int kt = 0; kt < nkt; kt++) {
        const int buf = kt & 1;
        CP_WAIT0;
        __syncthreads();
        if (kt + 1 < nkt) load_stage(kt + 1, buf ^ 1);

        const uint32_t Abase = AsU + buf*TBUF*2 + aOff + (wm*64*AST)*2;
        const uint32_t Bbase = BsU + buf*TBUF*2 + bOff + (wn*32*AST)*2;
        #pragma unroll
        for (int ks = 0; ks < 2; ks++) {
            unsigned a[4][4];
            #pragma unroll
            for (int mt = 0; mt < 4; mt++)
                ldsm4(a[mt], Abase + (mt*16*AST + ks*16)*2);
            unsigned b[4][2];
            #pragma unroll
            for (int nt2 = 0; nt2 < 2; nt2++) {
                unsigned bb[4];
                ldsm4(bb, Bbase + (nt2*16*AST + ks*16)*2);
                b[2*nt2][0]   = bb[0]; b[2*nt2][1]   = bb[1];
                b[2*nt2+1][0] = bb[2]; b[2*nt2+1][1] = bb[3];
            }
            #pragma unroll
            for (int mt = 0; mt < 4; mt++)
                #pragma unroll
                for (int nt = 0; nt < 4; nt++)
                    mma_f16(d[mt][nt], a[mt], b[nt]);
        }
    }

    if (MODE == 3) __syncthreads();

    #pragma unroll
    for (int mt = 0; mt < 4; mt++) {
        #pragma unroll
        for (int nt = 0; nt < 4; nt++) {
            const int lc   = wn*32 + nt*8 + 2*tig;
            const int col  = bn0 + lc;
            const float b0 = bias[col], b1 = bias[col + 1];
            const int r0l  = wm*64 + mt*16 + g;
            const int row0 = bm0 + r0l;
            float v0 = d[mt][nt][0] + b0;
            float v1 = d[mt][nt][1] + b1;
            float v2 = d[mt][nt][2] + b0;
            float v3 = d[mt][nt][3] + b1;
            if (MODE == 4) {
                v0 = 0.5f*v0*(1.0f + erff(v0*0.70710678118654752f));
                v1 = 0.5f*v1*(1.0f + erff(v1*0.70710678118654752f));
                v2 = 0.5f*v2*(1.0f + erff(v2*0.70710678118654752f));
                v3 = 0.5f*v3*(1.0f + erff(v3*0.70710678118654752f));
            }
            if (MODE == 2) { v0 *= QSCALE; v1 *= QSCALE; v2 *= QSCALE; v3 *= QSCALE; }
            if (MODE == 0) {
                float* C = (float*)Cout;
                *(float2*)(C + (size_t)row0 * N + col)       = make_float2(v0, v1);
                *(float2*)(C + (size_t)(row0 + 8) * N + col) = make_float2(v2, v3);
            } else if (MODE == 3) {
                __half* st = hsm;   // [128 cols][136]
                st[lc*136 + r0l]         = __float2half(v0);
                st[(lc+1)*136 + r0l]     = __float2half(v1);
                st[lc*136 + r0l + 8]     = __float2half(v2);
                st[(lc+1)*136 + r0l + 8] = __float2half(v3);
            } else {
                __half* C = (__half*)Cout;
                *(unsigned*)(C + (size_t)row0 * N + col)       = h2u(v0, v1);
                *(unsigned*)(C + (size_t)(row0 + 8) * N + col) = h2u(v2, v3);
            }
        }
    }

    if (MODE == 3) {
        __syncthreads();
        __half* st = hsm;
        __half* vt = (__half*)Cout;
        const int bb = bm0 >> 11;
        const int s0 = bm0 & (SEQ - 1);
        #pragma unroll
        for (int i = 0; i < 8; i++) {
            const int j  = tid + i*256;
            const int c  = j >> 4, ch = j & 15;
            const int cg = bn0 + c;
            const int hh = cg >> 6, dd = cg & 63;
            const size_t dst = (((size_t)bb*NH + hh)*HDIM + dd)*SEQ + s0 + ch*8;
            *(uint4*)(vt + dst) = *(const uint4*)&st[c*136 + ch*8];
        }
    }
}

// ============== FP16 flash attention (BQ=128, BKV=64, 2-stage) ==============
#define BQ  128
#define BKV 64
#define AKST 72
#define KBUFH (BKV*AKST)
#define ATTN_SMEM ((4*KBUFH + BQ*AKST) * 2)   // 55296 B

__global__ void __launch_bounds__(256, 2) attn_h(
    const __half* __restrict__ Q, const __half* __restrict__ K,
    const __half* __restrict__ VT, __half* __restrict__ O)
{
    extern __shared__ __half hsm[];
    __half* Ks = hsm;
    __half* Vs = hsm + 2*KBUFH;

    const int tid  = threadIdx.x;
    const int wid  = tid >> 5, lane = tid & 31;
    const int g    = lane >> 2, tig = lane & 3;
    const int qt = blockIdx.x, h = blockIdx.y, b = blockIdx.z;

    const size_t baseq  = ((size_t)(b*SEQ) + qt*BQ) * EDIM + h*HDIM;
    const size_t vtbase = ((size_t)(b*NH + h)) * HDIM * SEQ;

    const uint32_t smemU = (uint32_t)__cvta_generic_to_shared(hsm);
    const uint32_t KsU = smemU;
    const uint32_t VsU = smemU + 2*KBUFH*2;
    const uint32_t PwU = smemU + 4*KBUFH*2 + (wid*16)*AKST*2;
    const uint32_t aOff = (((lane&7) + (lane&8))*AKST + ((lane>>1)&8))*2;
    const uint32_t bOff = (((lane&7) + ((lane>>1)&8))*AKST + (lane&8))*2;

    unsigned qa[4][4];
    {
        const __half* qp = Q + baseq + (size_t)(wid*16) * EDIM;
        #pragma unroll
        for (int ks = 0; ks < 4; ks++) {
            const int k0 = ks*16 + 2*tig;
            qa[ks][0] = *(const unsigned*)(qp + (size_t)g*EDIM + k0);
            qa[ks][1] = *(const unsigned*)(qp + (size_t)(g+8)*EDIM + k0);
            qa[ks][2] = *(const unsigned*)(qp + (size_t)g*EDIM + k0 + 8);
            qa[ks][3] = *(const unsigned*)(qp + (size_t)(g+8)*EDIM + k0 + 8);
        }
    }

    float m0 = -1e30f, m1 = -1e30f, l0 = 0.f, l1 = 0.f;
    float o[8][4];
    #pragma unroll
    for (int nt = 0; nt < 8; nt++)
        #pragma unroll
        for (int j = 0; j < 4; j++) o[nt][j] = 0.f;

    const int lj = tid >> 3, lch = tid & 7;
    const __half* Kg0 = K  + ((size_t)(b*SEQ)) * EDIM + h*HDIM + (size_t)lj * EDIM + lch*8;
    const __half* Vg0 = VT + vtbase + (size_t)lj * SEQ + lch*8;
    const int nTiles = SEQ / BKV;

    #pragma unroll
    for (int i = 0; i < 2; i++) {
        cp16(&Ks[(lj + i*32)*AKST + lch*8], Kg0 + (size_t)(i*32) * EDIM);
        cp16(&Vs[(lj + i*32)*AKST + lch*8], Vg0 + (size_t)(i*32) * SEQ);
    }
    CP_COMMIT;

    for (int t = 0; t < nTiles; t++) {
        const int buf = t & 1;
        CP_WAIT0;
        __syncthreads();

        if (t + 1 < nTiles) {
            __half* Kn = Ks + (buf^1) * KBUFH;
            __half* Vn = Vs + (buf^1) * KBUFH;
            const size_t koff = (size_t)(t+1) * BKV * EDIM;
            const size_t voff = (size_t)(t+1) * BKV;
            #pragma unroll
            for (int i = 0; i < 2; i++) {
                cp16(&Kn[(lj + i*32)*AKST + lch*8], Kg0 + koff + (size_t)(i*32) * EDIM);
                cp16(&Vn[(lj + i*32)*AKST + lch*8], Vg0 + voff + (size_t)(i*32) * SEQ);
            }
            CP_COMMIT;
        }

        // S = Q @ K^T
        const uint32_t Kbase = KsU + buf*KBUFH*2 + bOff;
        float s[8][4];
        #pragma unroll
        for (int nt = 0; nt < 8; nt++)
            #pragma unroll
            for (int j = 0; j < 4; j++) s[nt][j] = 0.f;
        #pragma unroll
        for (int ks = 0; ks < 4; ks++) {
            #pragma unroll
            for (int nt2 = 0; nt2 < 4; nt2++) {
                unsigned bb[4];
                ldsm4(bb, Kbase + (nt2*16*AKST + ks*16)*2);
                unsigned b0[2] = {bb[0], bb[1]};
                unsigned b1[2] = {bb[2], bb[3]};
                mma_f16(s[2*nt2],   qa[ks], b0);
                mma_f16(s[2*nt2+1], qa[ks], b1);
            }
        }

        // online softmax (log2 domain)
        float rm0 = -1e30f, rm1 = -1e30f;
        #pragma unroll
        for (int nt = 0; nt < 8; nt++) {
            rm0 = fmaxf(rm0, fmaxf(s[nt][0], s[nt][1]));
            rm1 = fmaxf(rm1, fmaxf(s[nt][2], s[nt][3]));
        }
        #pragma unroll
        for (int off = 1; off < 4; off <<= 1) {
            rm0 = fmaxf(rm0, __shfl_xor_sync(0xffffffffu, rm0, off));
            rm1 = fmaxf(rm1, __shfl_xor_sync(0xffffffffu, rm1, off));
        }
        const float M0 = fmaxf(m0, rm0), M1 = fmaxf(m1, rm1);
        const float a0 = ex2f(m0 - M0), a1 = ex2f(m1 - M1);
        float sum0 = 0.f, sum1 = 0.f;
        #pragma unroll
        for (int nt = 0; nt < 8; nt++) {
            s[nt][0] = ex2f(s[nt][0] - M0);
            s[nt][1] = ex2f(s[nt][1] - M0);
            s[nt][2] = ex2f(s[nt][2] - M1);
            s[nt][3] = ex2f(s[nt][3] - M1);
            sum0 += s[nt][0] + s[nt][1];
            sum1 += s[nt][2] + s[nt][3];
        }
        #pragma unroll
        for (int off = 1; off < 4; off <<= 1) {
            sum0 += __shfl_xor_sync(0xffffffffu, sum0, off);
            sum1 += __shfl_xor_sync(0xffffffffu, sum1, off);
        }
        l0 = l0*a0 + sum0;  l1 = l1*a1 + sum1;
        m0 = M0;            m1 = M1;
        #pragma unroll
        for (int nt = 0; nt < 8; nt++) {
            o[nt][0] *= a0; o[nt][1] *= a0;
            o[nt][2] *= a1; o[nt][3] *= a1;
        }

        // store P via stmatrix (warp-private rows)
        #pragma unroll
        for (int nt2 = 0; nt2 < 4; nt2++) {
            stsm4(PwU + aOff - ((lane>>1)&8)*2 + ((lane>>1)&8)*2 + nt2*16*2,
                  h2u(s[2*nt2][0],   s[2*nt2][1]),
                  h2u(s[2*nt2][2],   s[2*nt2][3]),
                  h2u(s[2*nt2+1][0], s[2*nt2+1][1]),
                  h2u(s[2*nt2+1][2], s[2*nt2+1][3]));
        }
        __syncwarp();

        // O += P @ V
        const uint32_t Vbase = VsU + buf*KBUFH*2 + bOff;
        #pragma unroll
        for (int ks = 0; ks < 4; ks++) {
            unsigned pa[4];
            ldsm4(pa, PwU + aOff + ks*16*2);
            #pragma unroll
            for (int nt2 = 0; nt2 < 4; nt2++) {
                unsigned bb[4];
                ldsm4(bb, Vbase + (nt2*16*AKST + ks*16)*2);
                unsigned b0[2] = {bb[0], bb[1]};
                unsigned b1[2] = {bb[2], bb[3]};
                mma_f16(o[2*nt2],   pa, b0);
                mma_f16(o[2*nt2+1], pa, b1);
            }
        }
    }

    const float inv0 = 1.0f / l0, inv1 = 1.0f / l1;
    __half* Og = O + baseq + (size_t)(wid*16) * EDIM;
    #pragma unroll
    for (int nt = 0; nt < 8; nt++) {
        const int col = nt*8 + 2*tig;
        *(unsigned*)(Og + (size_t)g*EDIM + col)     = h2u(o[nt][0]*inv0, o[nt][1]*inv0);
        *(unsigned*)(Og + (size_t)(g+8)*EDIM + col) = h2u(o[nt][2]*inv1, o[nt][3]*inv1);
    }
}

// ---------------- fused residual + LayerNorm (warp per row) -----------------
template<int WRITE_HALF>
__global__ void __launch_bounds__(256) ln_kernel(
    const float* __restrict__ X, const float* __restrict__ Y,
    const float* __restrict__ gamma, const float* __restrict__ beta,
    float* __restrict__ outF, __half* __restrict__ outH)
{
    const int lane = threadIdx.x & 31;
    const int row  = blockIdx.x * 8 + (threadIdx.x >> 5);

    float4 v[4];
    float sum = 0.f, sq = 0.f;
    #pragma unroll
    for (int i = 0; i < 4; i++) {
        const int c = (i*32 + lane) * 4;
        float4 xv = *(const float4*)(X + (size_t)row*EDIM + c);
        float4 yv = *(const float4*)(Y + (size_t)row*EDIM + c);
        v[i].x = xv.x + yv.x; v[i].y = xv.y + yv.y;
        v[i].z = xv.z + yv.z; v[i].w = xv.w + yv.w;
        sum += v[i].x + v[i].y + v[i].z + v[i].w;
        sq  += v[i].x*v[i].x + v[i].y*v[i].y + v[i].z*v[i].z + v[i].w*v[i].w;
    }
    #pragma unroll
    for (int off = 16; off > 0; off >>= 1) {
        sum += __shfl_xor_sync(0xffffffffu, sum, off);
        sq  += __shfl_xor_sync(0xffffffffu, sq, off);
    }
    const float mu   = sum * (1.0f/EDIM);
    const float var  = sq * (1.0f/EDIM) - mu*mu;
    const float rstd = rsqrtf(var + 1e-5f);

    #pragma unroll
    for (int i = 0; i < 4; i++) {
        const int c = (i*32 + lane) * 4;
        float4 gv = *(const float4*)(gamma + c);
        float4 bv = *(const float4*)(beta  + c);
        float4 ov;
        ov.x = (v[i].x - mu)*rstd*gv.x + bv.x;
        ov.y = (v[i].y - mu)*rstd*gv.y + bv.y;
        ov.z = (v[i].z - mu)*rstd*gv.z + bv.z;
        ov.w = (v[i].w - mu)*rstd*gv.w + bv.w;
        *(float4*)(outF + (size_t)row*EDIM + c) = ov;
        if (WRITE_HALF) {
            *(unsigned*)(outH + (size_t)row*EDIM + c)     = h2u(ov.x, ov.y);
            *(unsigned*)(outH + (size_t)row*EDIM + c + 2) = h2u(ov.z, ov.w);
        }
    }
}

// ---------------- converts --------------------------------------------------
__global__ void __launch_bounds__(256) f2h(const float* __restrict__ in,
                                           __half* __restrict__ out, int n)
{
    const int i = (blockIdx.x * 256 + threadIdx.x) * 4;
    if (i >= n) return;
    float4 v = *(const float4*)(in + i);
    *(unsigned*)(out + i)     = h2u(v.x, v.y);
    *(unsigned*)(out + i + 2) = h2u(v.z, v.w);
}

__global__ void __launch_bounds__(256) tconv(const float* __restrict__ in,
                                             __half* __restrict__ out, int K, int N)
{
    __shared__ float t[32][33];
    const int bx = blockIdx.x * 32;
    const int by = blockIdx.y * 32;
    const int x = threadIdx.x & 31, y = threadIdx.x >> 5;
    #pragma unroll
    for (int i = 0; i < 32; i += 8)
        t[y + i][x] = in[(size_t)(by + y + i)*N + bx + x];
    __syncthreads();
    #pragma unroll
    for (int i = 0; i < 32; i += 8)
        out[(size_t)(bx + y + i)*K + by + x] = __float2half(t[x][y + i]);
}

// ---------------- launch ----------------------------------------------------
extern "C" void kernel_launch(void* const* d_in, const int* in_sizes, int n_in,
                              void* d_out, int out_size)
{
    const float* query = (const float*)d_in[0];
    const float* key   = (const float*)d_in[1];
    const float* value = (const float*)d_in[2];
    const float* Wq = (const float*)d_in[3];  const float* bq = (const float*)d_in[4];
    const float* Wk = (const float*)d_in[5];  const float* bk = (const float*)d_in[6];
    const float* Wv = (const float*)d_in[7];  const float* bv = (const float*)d_in[8];
    const float* Wo = (const float*)d_in[9];  const float* bo = (const float*)d_in[10];
    const float* g1 = (const float*)d_in[11]; const float* be1 = (const float*)d_in[12];
    const float* g2 = (const float*)d_in[13]; const float* be2 = (const float*)d_in[14];
    const float* W1 = (const float*)d_in[15]; const float* b1 = (const float*)d_in[16];
    const float* W2 = (const float*)d_in[17]; const float* b2 = (const float*)d_in[18];
    float* out = (float*)d_out;

    __half *qin, *kin, *vin, *qh, *kh, *vt, *ctxh, *ln1h, *hh, *wt;
    float  *tmp, *ln1;
    cudaGetSymbolAddress((void**)&qin,  g_qin_h);
    cudaGetSymbolAddress((void**)&kin,  g_kin_h);
    cudaGetSymbolAddress((void**)&vin,  g_vin_h);
    cudaGetSymbolAddress((void**)&qh,   g_qh);
    cudaGetSymbolAddress((void**)&kh,   g_kh);
    cudaGetSymbolAddress((void**)&vt,   g_vt);
    cudaGetSymbolAddress((void**)&ctxh, g_ctxh);
    cudaGetSymbolAddress((void**)&tmp,  g_tmp);
    cudaGetSymbolAddress((void**)&ln1,  g_ln1);
    cudaGetSymbolAddress((void**)&ln1h, g_ln1h);
    cudaGetSymbolAddress((void**)&hh,   g_hh);
    cudaGetSymbolAddress((void**)&wt,   g_wt);

    __half* WqT = wt;
    __half* WkT = wt + 1*EDIM*EDIM;
    __half* WvT = wt + 2*EDIM*EDIM;
    __half* WoT = wt + 3*EDIM*EDIM;
    __half* W1T = wt + 4*EDIM*EDIM;
    __half* W2T = wt + 4*EDIM*EDIM + EDIM*FFN;

    cudaFuncSetAttribute(gemm_h<0>, cudaFuncAttributeMaxDynamicSharedMemorySize, GEMM_SMEM);
    cudaFuncSetAttribute(gemm_h<1>, cudaFuncAttributeMaxDynamicSharedMemorySize, GEMM_SMEM);
    cudaFuncSetAttribute(gemm_h<2>, cudaFuncAttributeMaxDynamicSharedMemorySize, GEMM_SMEM);
    cudaFuncSetAttribute(gemm_h<3>, cudaFuncAttributeMaxDynamicSharedMemorySize, GEMM_SMEM);
    cudaFuncSetAttribute(gemm_h<4>, cudaFuncAttributeMaxDynamicSharedMemorySize, GEMM_SMEM);
    cudaFuncSetAttribute(attn_h,    cudaFuncAttributeMaxDynamicSharedMemorySize, ATTN_SMEM);

    const int NE = MROWS*EDIM;
    f2h<<<NE/1024, 256>>>(query, qin, NE);
    f2h<<<NE/1024, 256>>>(key,   kin, NE);
    f2h<<<NE/1024, 256>>>(value, vin, NE);
    tconv<<<dim3(EDIM/32, EDIM/32), 256>>>(Wq, WqT, EDIM, EDIM);
    tconv<<<dim3(EDIM/32, EDIM/32), 256>>>(Wk, WkT, EDIM, EDIM);
    tconv<<<dim3(EDIM/32, EDIM/32), 256>>>(Wv, WvT, EDIM, EDIM);
    tconv<<<dim3(EDIM/32, EDIM/32), 256>>>(Wo, WoT, EDIM, EDIM);
    tconv<<<dim3(FFN/32,  EDIM/32), 256>>>(W1, W1T, EDIM, FFN);
    tconv<<<dim3(EDIM/32, FFN/32),  256>>>(W2, W2T, FFN, EDIM);

    dim3 gProj(EDIM/128, MROWS/128);
    dim3 gF1(FFN/128,  MROWS/128);

    gemm_h<2><<<gProj, 256, GEMM_SMEM>>>(qin, WqT, bq, qh, MROWS, EDIM, EDIM);
    gemm_h<1><<<gProj, 256, GEMM_SMEM>>>(kin, WkT, bk, kh, MROWS, EDIM, EDIM);
    gemm_h<3><<<gProj, 256, GEMM_SMEM>>>(vin, WvT, bv, vt, MROWS, EDIM, EDIM);

    attn_h<<<dim3(SEQ/BQ, NH, BATCH), 256, ATTN_SMEM>>>(qh, kh, vt, ctxh);

    gemm_h<0><<<gProj, 256, GEMM_SMEM>>>(ctxh, WoT, bo, tmp, MROWS, EDIM, EDIM);
    ln_kernel<1><<<MROWS/8, 256>>>(query, tmp, g1, be1, ln1, ln1h);

    gemm_h<4><<<gF1, 256, GEMM_SMEM>>>(ln1h, W1T, b1, hh, MROWS, FFN, EDIM);
    gemm_h<0><<<gProj, 256, GEMM_SMEM>>>(hh, W2T, b2, tmp, MROWS, EDIM, FFN);
    ln_kernel<0><<<MROWS/8, 256>>>(ln1, tmp, g2, be2, out, nullptr);
}